// round 15
// baseline (speedup 1.0000x reference)
#include <cuda_runtime.h>
#include <cuda_bf16.h>
#include <cuda_fp16.h>
#include <cstdint>

#define N_NODES 10000
#define N_EDGES 100000
#define DIN 64
#define H 64
#define EIN 16
#define EH 128
#define STEPS 3
#define KC2 192          // fp16 3-pass split K
#define TCOLS 8192
#define CHUNK 2048
#define NCH 5            // ceil(10000/2048)

// ---------------- device scratch ----------------
__device__ float g_x[N_NODES * H];
__device__ __half g_xc[N_NODES * KC2];            // [x_hi | x_hi | x_lo]
__device__ float g_agg[N_NODES * H];
__device__ __half g_h1s[(size_t)N_EDGES * 256];   // h1 fp16 split [hi(128)|lo(128)]
__device__ __half g_WtC[TCOLS * KC2];             // col'=o*128+k: [W_hi | W_lo | W_hi]
__device__ __half g_T[2 * (size_t)CHUNK * TCOLS]; // double-buffered chunk T (2x32MB, L2)
__device__ float g_B[N_NODES * H];
__device__ int g_cnt[N_NODES];
__device__ int g_fill[N_NODES];
__device__ int g_rowptr[N_NODES + 1];
__device__ int g_eidx[N_EDGES];
__device__ float g_sum[H];
__device__ float g_sumsq[H];

// ---------------- helpers ----------------
__device__ __forceinline__ uint32_t smem_u32(const void* p) {
    uint32_t a;
    asm("{ .reg .u64 t; cvta.to.shared.u64 t, %1; cvt.u32.u64 %0, t; }" : "=r"(a) : "l"(p));
    return a;
}
__device__ __forceinline__ void cp_async16(uint32_t dst, const void* src, int src_bytes) {
    asm volatile("cp.async.cg.shared.global [%0], [%1], 16, %2;"
                 :: "r"(dst), "l"(src), "r"(src_bytes));
}
#define CP_COMMIT() asm volatile("cp.async.commit_group;" ::: "memory")
#define CP_WAIT(n)  asm volatile("cp.async.wait_group %0;" :: "n"(n) : "memory")

__device__ __forceinline__ void ldsm_x4(uint32_t& r0, uint32_t& r1, uint32_t& r2,
                                        uint32_t& r3, uint32_t addr) {
    asm volatile("ldmatrix.sync.aligned.m8n8.x4.shared.b16 {%0,%1,%2,%3}, [%4];"
                 : "=r"(r0), "=r"(r1), "=r"(r2), "=r"(r3) : "r"(addr));
}
__device__ __forceinline__ void mma_fp16(float& c0, float& c1, float& c2, float& c3,
                                         uint32_t a0, uint32_t a1, uint32_t a2, uint32_t a3,
                                         uint32_t b0, uint32_t b1) {
    asm volatile(
        "mma.sync.aligned.m16n8k16.row.col.f32.f16.f16.f32 "
        "{%0,%1,%2,%3}, {%4,%5,%6,%7}, {%8,%9}, {%0,%1,%2,%3};"
        : "+f"(c0), "+f"(c1), "+f"(c2), "+f"(c3)
        : "r"(a0), "r"(a1), "r"(a2), "r"(a3), "r"(b0), "r"(b1));
}
__device__ __forceinline__ void split_store16(float v, __half* row, int j) {
    __half hi = __float2half(v);
    __half lo = __float2half(v - __half2float(hi));
    row[j] = hi;
    row[64 + j] = hi;
    row[128 + j] = lo;
}

// ---------------- node MLP (x, x-split, B for step 0, agg init, BN zero) ----------------
__global__ void node_mlp(const float* __restrict__ nf, const float* __restrict__ W0,
                         const float* __restrict__ b0, const float* __restrict__ be2,
                         const float* __restrict__ conv_bias) {
    int n = blockIdx.x;
    int h = threadIdx.x;
    __shared__ float xs[DIN];
    __shared__ float vs[64];
    if (n == 0) { g_sum[h] = 0.f; g_sumsq[h] = 0.f; }
    xs[h] = nf[n * DIN + h];
    __syncthreads();
    float acc = b0[h];
#pragma unroll
    for (int i = 0; i < DIN; i++) acc += xs[i] * W0[i * H + h];
    float v = fmaxf(acc, 0.0f);
    g_x[n * H + h] = v;
    split_store16(v, g_xc + n * KC2, h);
    g_agg[n * H + h] = conv_bias[h];
    vs[h] = v;
    __syncthreads();
    float accB = 0.f;
#pragma unroll
    for (int j = 0; j < 64; j++) accB += vs[j] * be2[j * 64 + h];
    g_B[n * 64 + h] = accB;
}

// ---------------- edge hidden -> fp16 2-term split ----------------
__global__ void edge_h1(const float* __restrict__ ef, const float* __restrict__ We1,
                        const float* __restrict__ be1) {
    int gid = blockIdx.x * blockDim.x + threadIdx.x;
    int e = gid >> 7;
    int k = gid & 127;
    if (e >= N_EDGES) return;
    float acc = be1[k];
#pragma unroll
    for (int i = 0; i < EIN; i++) acc += ef[e * EIN + i] * We1[i * EH + k];
    float v = fmaxf(acc, 0.0f);
    __half hi = __float2half(v);
    __half lo = __float2half(v - __half2float(hi));
    g_h1s[(size_t)e * 256 + k] = hi;
    g_h1s[(size_t)e * 256 + 128 + k] = lo;
}

// ---------------- W' prep: col' = o*128 + k; row = [W_hi | W_lo | W_hi] ----------------
__global__ void wt_prep(const float* __restrict__ We2) {
    int idx = blockIdx.x * blockDim.x + threadIdx.x;
    if (idx >= TCOLS * 64) return;
    int colp = idx >> 6;
    int j = idx & 63;
    int k = colp & 127;
    int o = colp >> 7;
    float v = We2[k * 4096 + j * 64 + o];
    __half hi = __float2half(v);
    __half lo = __float2half(v - __half2float(hi));
    __half* row = g_WtC + colp * KC2;
    row[j] = hi;
    row[64 + j] = lo;
    row[128 + j] = hi;
}

// ---------------- edge sort by src ----------------
__global__ void zero_bins() {
    int i = blockIdx.x * blockDim.x + threadIdx.x;
    if (i < N_NODES) { g_cnt[i] = 0; g_fill[i] = 0; }
}
__global__ void hist_kernel(const int* __restrict__ src) {
    int e = blockIdx.x * blockDim.x + threadIdx.x;
    if (e < N_EDGES) atomicAdd(&g_cnt[src[e]], 1);
}
__global__ void scan_kernel() {
    __shared__ int ts[1024];
    int t = threadIdx.x;
    int base = t * 10;
    int c[10];
    int tot = 0;
#pragma unroll
    for (int i = 0; i < 10; i++) {
        int idx = base + i;
        c[i] = (idx < N_NODES) ? g_cnt[idx] : 0;
        tot += c[i];
    }
    ts[t] = tot;
    __syncthreads();
    for (int off = 1; off < 1024; off <<= 1) {
        int v = (t >= off) ? ts[t - off] : 0;
        __syncthreads();
        ts[t] += v;
        __syncthreads();
    }
    int run = ts[t] - tot;
#pragma unroll
    for (int i = 0; i < 10; i++) {
        int idx = base + i;
        if (idx < N_NODES) { g_rowptr[idx] = run; run += c[i]; }
    }
    if (t == 1023) g_rowptr[N_NODES] = N_EDGES;
}
__global__ void scatter_kernel(const int* __restrict__ src) {
    int e = blockIdx.x * blockDim.x + threadIdx.x;
    if (e >= N_EDGES) return;
    int s = src[e];
    int pos = g_rowptr[s] + atomicAdd(&g_fill[s], 1);
    g_eidx[pos] = e;
}

// ---------------- T-GEMM: 3-pass fp16, K=192, chunked ----------------
#define BKT 64
#define STAGE_BYTES 32768
#define TG_SMEM (3 * STAGE_BYTES)
#define NKT2 3

__global__ void __launch_bounds__(128, 2) tgemm(int chunk_base, int buf) {
    extern __shared__ char smem[];
    const uint32_t sbase = smem_u32(smem);
    const int tid = threadIdx.x;
    const int wid = tid >> 5;
    const int lane = tid & 31;
    const int block_n = blockIdx.x * 128;
    const int block_m = blockIdx.y * 128;   // local row within chunk
    __half* Tout = g_T + (size_t)buf * CHUNK * TCOLS;

    const int wm = wid & 1;
    const int wn = wid >> 1;
    const int m_off = wm * 64;
    const int n_off = wn * 64;

    float acc[4][8][4];
#pragma unroll
    for (int mt = 0; mt < 4; mt++)
#pragma unroll
        for (int nt = 0; nt < 8; nt++)
#pragma unroll
            for (int q = 0; q < 4; q++) acc[mt][nt][q] = 0.0f;

    auto load_stage = [&](int stage, int kt) {
        const int k0 = kt * BKT;
        const uint32_t As = sbase + stage * STAGE_BYTES;
        const uint32_t Bs = As + 16384;
#pragma unroll
        for (int i = 0; i < 8; i++) {
            int cid = tid + i * 128;
            int r = cid >> 3;
            int c = cid & 7;
            int n = chunk_base + block_m + r;
            const void* gsrc = g_xc + (size_t)n * KC2 + k0 + c * 8;
            uint32_t sdst = As + r * 128 + ((c ^ (r & 7)) << 4);
            cp_async16(sdst, gsrc, (n < N_NODES) ? 16 : 0);
        }
#pragma unroll
        for (int i = 0; i < 8; i++) {
            int cid = tid + i * 128;
            int r = cid >> 3;
            int c = cid & 7;
            int col = block_n + r;
            const void* gsrc = g_WtC + (size_t)col * KC2 + k0 + c * 8;
            uint32_t sdst = Bs + r * 128 + ((c ^ (r & 7)) << 4);
            cp_async16(sdst, gsrc, 16);
        }
    };

    const int a_row_l = lane & 15;
    const int a_uoff = lane >> 4;
    const int b_row_l = ((lane >> 4) << 3) + (lane & 7);
    const int b_uoff = (lane >> 3) & 1;

    load_stage(0, 0);
    CP_COMMIT();
    load_stage(1, 1);
    CP_COMMIT();

#pragma unroll
    for (int kt = 0; kt < NKT2; kt++) {
        if (kt == NKT2 - 1) { CP_WAIT(0); } else { CP_WAIT(1); }
        __syncthreads();
        if (kt + 2 < NKT2) {
            load_stage(kt + 2, kt + 2);
            CP_COMMIT();
        }
        const uint32_t As = sbase + kt * STAGE_BYTES;
        const uint32_t Bs = As + 16384;
#pragma unroll
        for (int ks = 0; ks < 4; ks++) {
            const int ub = ks * 2;
            uint32_t a[4][4];
#pragma unroll
            for (int mt = 0; mt < 4; mt++) {
                int r = m_off + mt * 16 + a_row_l;
                int u = ub + a_uoff;
                ldsm_x4(a[mt][0], a[mt][1], a[mt][2], a[mt][3],
                        As + r * 128 + ((u ^ (r & 7)) << 4));
            }
            uint32_t b[8][2];
#pragma unroll
            for (int np = 0; np < 4; np++) {
                int r = n_off + np * 16 + b_row_l;
                int u = ub + b_uoff;
                uint32_t r0, r1, r2, r3;
                ldsm_x4(r0, r1, r2, r3, Bs + r * 128 + ((u ^ (r & 7)) << 4));
                b[np * 2][0] = r0; b[np * 2][1] = r1;
                b[np * 2 + 1][0] = r2; b[np * 2 + 1][1] = r3;
            }
#pragma unroll
            for (int mt = 0; mt < 4; mt++)
#pragma unroll
                for (int nt = 0; nt < 8; nt++)
                    mma_fp16(acc[mt][nt][0], acc[mt][nt][1], acc[mt][nt][2], acc[mt][nt][3],
                             a[mt][0], a[mt][1], a[mt][2], a[mt][3],
                             b[nt][0], b[nt][1]);
        }
        __syncthreads();
    }

    const int qrow = lane >> 2;
    const int qcol = (lane & 3) * 2;
#pragma unroll
    for (int mt = 0; mt < 4; mt++) {
        int lr0 = block_m + m_off + mt * 16 + qrow;   // local chunk row
        int lr1 = lr0 + 8;
#pragma unroll
        for (int nt = 0; nt < 8; nt++) {
            int col = block_n + n_off + nt * 8 + qcol;
            if (chunk_base + lr0 < N_NODES)
                *(__half2*)(Tout + (size_t)lr0 * TCOLS + col) =
                    __floats2half2_rn(acc[mt][nt][0], acc[mt][nt][1]);
            if (chunk_base + lr1 < N_NODES)
                *(__half2*)(Tout + (size_t)lr1 * TCOLS + col) =
                    __floats2half2_rn(acc[mt][nt][2], acc[mt][nt][3]);
        }
    }
}

// ---------------- msg v3: tensor-core per-node GEMM, 16-edge chunks ----------------
#define MSG_T_OFF 0
#define MSG_H_OFF 16384
#define MSG_DS_OFF 24576
#define MSG_BS_OFF 24640
#define MSG_SMEM 24896

__global__ void __launch_bounds__(128) msg_kernel3(const int* __restrict__ dst,
                                                   int chunk_base, int buf) {
    __shared__ __align__(16) char sm[MSG_SMEM];
    int s = chunk_base + blockIdx.x;
    if (s >= N_NODES) return;
    int beg = g_rowptr[s];
    int end = g_rowptr[s + 1];
    if (beg == end) return;
    const uint32_t sbase = smem_u32(sm);
    int tid = threadIdx.x;
    int wn = tid >> 5;
    int lane = tid & 31;
    int* ds = (int*)(sm + MSG_DS_OFF);
    float* Bs = (float*)(sm + MSG_BS_OFF);

    const uint4* Tg = (const uint4*)(g_T + (size_t)buf * CHUNK * TCOLS +
                                     (size_t)blockIdx.x * TCOLS);
#pragma unroll
    for (int i = 0; i < 8; i++) {
        int idx = tid + i * 128;
        int r = idx >> 4;
        int u = idx & 15;
        int su = (u & 8) | ((u ^ r) & 7);
        *(uint4*)(sm + MSG_T_OFF + r * 256 + su * 16) = Tg[idx];
    }
    if (tid < 64) Bs[tid] = g_B[s * 64 + tid];
    __syncthreads();

    uint32_t bf[8][4];
    {
        int brow = wn * 16 + ((lane >> 4) << 3) + (lane & 7);
        int uoff = (lane >> 3) & 1;
#pragma unroll
        for (int kc = 0; kc < 8; kc++) {
            int u = kc * 2 + uoff;
            int su = (u & 8) | ((u ^ brow) & 7);
            ldsm_x4(bf[kc][0], bf[kc][1], bf[kc][2], bf[kc][3],
                    sbase + MSG_T_OFF + brow * 256 + su * 16);
        }
    }

    const int arow = lane & 15;
    const int auoff = lane >> 4;

    for (int base = beg; base < end; base += 16) {
        int ne = end - base;
        if (ne > 16) ne = 16;
        if (tid < 16) ds[tid] = (tid < ne) ? dst[g_eidx[base + tid]] : 0;
#pragma unroll
        for (int i = 0; i < 4; i++) {
            int idx = tid + i * 128;
            int r = idx >> 5;
            int u = idx & 31;
            uint4 v = make_uint4(0, 0, 0, 0);
            if (r < ne) {
                int e = g_eidx[base + r];
                v = *(const uint4*)(g_h1s + (size_t)e * 256 + u * 8);
            }
            int su = (u & 24) | ((u ^ r) & 7);
            *(uint4*)(sm + MSG_H_OFF + r * 512 + su * 16) = v;
        }
        __syncthreads();

        float c0[4] = {0.f, 0.f, 0.f, 0.f};
        float c1[4] = {0.f, 0.f, 0.f, 0.f};
#pragma unroll
        for (int kc = 0; kc < 16; kc++) {
            int u = kc * 2 + auoff;
            int su = (u & 24) | ((u ^ arow) & 7);
            uint32_t a0, a1, a2, a3;
            ldsm_x4(a0, a1, a2, a3, sbase + MSG_H_OFF + arow * 512 + su * 16);
            int bk = kc & 7;
            mma_fp16(c0[0], c0[1], c0[2], c0[3], a0, a1, a2, a3, bf[bk][0], bf[bk][1]);
            mma_fp16(c1[0], c1[1], c1[2], c1[3], a0, a1, a2, a3, bf[bk][2], bf[bk][3]);
        }

        int r0 = lane >> 2;
#pragma unroll
        for (int nt = 0; nt < 2; nt++) {
            int col = wn * 16 + nt * 8 + 2 * (lane & 3);
            float bx = Bs[col];
            float by = Bs[col + 1];
            const float* cc = nt ? c1 : c0;
            if (r0 < ne) {
                int dd = ds[r0];
                atomicAdd(&g_agg[dd * H + col], cc[0] + bx);
                atomicAdd(&g_agg[dd * H + col + 1], cc[1] + by);
            }
            if (r0 + 8 < ne) {
                int dd = ds[r0 + 8];
                atomicAdd(&g_agg[dd * H + col], cc[2] + bx);
                atomicAdd(&g_agg[dd * H + col + 1], cc[3] + by);
            }
        }
        __syncthreads();
    }
}

// ---------------- relu step for steps 0..STEPS-2 ----------------
__global__ void relu_step_b(const float* __restrict__ be2,
                            const float* __restrict__ conv_bias) {
    int n = blockIdx.x;
    int o = threadIdx.x;
    __shared__ float xs[64];
    float v = fmaxf(g_agg[n * 64 + o], 0.0f);
    g_x[n * 64 + o] = v;
    split_store16(v, g_xc + n * KC2, o);
    g_agg[n * 64 + o] = conv_bias[o];
    xs[o] = v;
    __syncthreads();
    float acc = 0.f;
#pragma unroll
    for (int j = 0; j < 64; j++) acc += xs[j] * be2[j * 64 + o];
    g_B[n * 64 + o] = acc;
}

// ---------------- final step: relu + BN partial sums ----------------
__global__ void __launch_bounds__(256) relu_bn() {
    int t = threadIdx.x;
    int h = t & 63;
    int rsub = t >> 6;
    float s = 0.f, q = 0.f;
    for (int r = blockIdx.x * 4 + rsub; r < N_NODES; r += gridDim.x * 4) {
        float v = fmaxf(g_agg[r * H + h], 0.0f);
        g_x[r * H + h] = v;
        s += v;
        q += v * v;
    }
    __shared__ float ss[256], sq[256];
    ss[t] = s;
    sq[t] = q;
    __syncthreads();
    if (t < 64) {
        s = ss[t] + ss[t + 64] + ss[t + 128] + ss[t + 192];
        q = sq[t] + sq[t + 64] + sq[t + 128] + sq[t + 192];
        atomicAdd(&g_sum[h], s);
        atomicAdd(&g_sumsq[h], q);
    }
}

__global__ void bn_apply(const float* __restrict__ gamma, const float* __restrict__ beta,
                         float* __restrict__ out) {
    int i = blockIdx.x * blockDim.x + threadIdx.x;
    if (i >= N_NODES * H) return;
    int h = i & 63;
    float mean = g_sum[h] / (float)N_NODES;
    float var = g_sumsq[h] / (float)N_NODES - mean * mean;
    out[i] = (g_x[i] - mean) * rsqrtf(var + 1e-5f) * gamma[h] + beta[h];
}

// ---------------- launch ----------------
extern "C" void kernel_launch(void* const* d_in, const int* in_sizes, int n_in,
                              void* d_out, int out_size) {
    const float* n_feat    = (const float*)d_in[0];
    const float* e_feat    = (const float*)d_in[1];
    const int*   src       = (const int*)d_in[2];
    const int*   dst       = (const int*)d_in[3];
    const float* W0        = (const float*)d_in[4];
    const float* b0        = (const float*)d_in[5];
    const float* We1       = (const float*)d_in[6];
    const float* be1       = (const float*)d_in[7];
    const float* We2       = (const float*)d_in[8];
    const float* be2       = (const float*)d_in[9];
    const float* conv_bias = (const float*)d_in[10];
    const float* gamma     = (const float*)d_in[11];
    const float* beta      = (const float*)d_in[12];
    float* out = (float*)d_out;

    static cudaStream_t s_aux = nullptr;
    static cudaEvent_t ev_fork = nullptr, ev_join = nullptr, ev_mprep = nullptr;
    static cudaEvent_t ev_t[STEPS][NCH], ev_m[STEPS][NCH], ev_r[STEPS];
    if (!s_aux) {
        cudaStreamCreateWithFlags(&s_aux, cudaStreamNonBlocking);
        cudaEventCreateWithFlags(&ev_fork, cudaEventDisableTiming);
        cudaEventCreateWithFlags(&ev_join, cudaEventDisableTiming);
        cudaEventCreateWithFlags(&ev_mprep, cudaEventDisableTiming);
        for (int st = 0; st < STEPS; st++) {
            cudaEventCreateWithFlags(&ev_r[st], cudaEventDisableTiming);
            for (int c = 0; c < NCH; c++) {
                cudaEventCreateWithFlags(&ev_t[st][c], cudaEventDisableTiming);
                cudaEventCreateWithFlags(&ev_m[st][c], cudaEventDisableTiming);
            }
        }
    }

    cudaFuncSetAttribute(tgemm, cudaFuncAttributeMaxDynamicSharedMemorySize, TG_SMEM);

    // fork: sort chain on aux; node/weight/edge prep on main
    cudaEventRecord(ev_fork, 0);
    cudaStreamWaitEvent(s_aux, ev_fork, 0);
    zero_bins<<<(N_NODES + 255) / 256, 256, 0, s_aux>>>();
    hist_kernel<<<(N_EDGES + 255) / 256, 256, 0, s_aux>>>(src);
    scan_kernel<<<1, 1024, 0, s_aux>>>();
    scatter_kernel<<<(N_EDGES + 255) / 256, 256, 0, s_aux>>>(src);
    cudaEventRecord(ev_join, s_aux);

    node_mlp<<<N_NODES, 64>>>(n_feat, W0, b0, be2, conv_bias);
    wt_prep<<<(TCOLS * 64) / 256, 256>>>(We2);
    edge_h1<<<(N_EDGES * EH) / 256, 256>>>(e_feat, We1, be1);
    cudaEventRecord(ev_mprep, 0);
    cudaStreamWaitEvent(s_aux, ev_mprep, 0);  // tgemm needs g_xc, g_WtC
    cudaStreamWaitEvent(0, ev_join, 0);       // msg needs sort results

    int nh = N_NODES * H;
    dim3 tgrid(TCOLS / 128, CHUNK / 128);
    for (int step = 0; step < STEPS; step++) {
        for (int c = 0; c < NCH; c++) {
            int base = c * CHUNK;
            int buf = c & 1;
            if (c >= 2) cudaStreamWaitEvent(s_aux, ev_m[step][c - 2], 0);  // buf reuse
            tgemm<<<tgrid, 128, TG_SMEM, s_aux>>>(base, buf);
            cudaEventRecord(ev_t[step][c], s_aux);
            cudaStreamWaitEvent(0, ev_t[step][c], 0);
            msg_kernel3<<<CHUNK, 128>>>(dst, base, buf);
            cudaEventRecord(ev_m[step][c], 0);
        }
        if (step < STEPS - 1) {
            relu_step_b<<<N_NODES, 64>>>(be2, conv_bias);
        } else {
            relu_bn<<<100, 256>>>();
        }
        cudaEventRecord(ev_r[step], 0);
        cudaStreamWaitEvent(s_aux, ev_r[step], 0);  // next step's tgemm needs new x
    }

    bn_apply<<<(nh + 255) / 256, 256>>>(gamma, beta, out);
    (void)in_sizes; (void)n_in; (void)out_size;
}

// round 16
// speedup vs baseline: 1.1730x; 1.1730x over previous
#include <cuda_runtime.h>
#include <cuda_bf16.h>
#include <cuda_fp16.h>
#include <cstdint>

#define N_NODES 10000
#define N_EDGES 100000
#define DIN 64
#define H 64
#define EIN 16
#define EH 128
#define STEPS 3
#define KC2 128          // fp16 2-pass split K
#define TCOLS 8192

// ---------------- device scratch ----------------
__device__ float g_x[N_NODES * H];
__device__ __half g_xc[N_NODES * KC2];            // [x_hi(64) | x_lo(64)]
__device__ float g_agg[N_NODES * H];
__device__ __half g_h1s[(size_t)N_EDGES * 256];   // h1 fp16 split [hi(128)|lo(128)]
__device__ __half g_WtC[TCOLS * KC2];             // col'=o*128+k: [W_hi | W_hi]
__device__ __half g_T[(size_t)N_NODES * TCOLS];   // per node: [o][k] k-contiguous
__device__ float g_B[N_NODES * H];
__device__ int g_cnt[N_NODES];
__device__ int g_fill[N_NODES];
__device__ int g_rowptr[N_NODES + 1];
__device__ int g_eidx[N_EDGES];
__device__ float g_sum[H];
__device__ float g_sumsq[H];

// ---------------- helpers ----------------
__device__ __forceinline__ uint32_t smem_u32(const void* p) {
    uint32_t a;
    asm("{ .reg .u64 t; cvta.to.shared.u64 t, %1; cvt.u32.u64 %0, t; }" : "=r"(a) : "l"(p));
    return a;
}
__device__ __forceinline__ void cp_async16(uint32_t dst, const void* src, int src_bytes) {
    asm volatile("cp.async.cg.shared.global [%0], [%1], 16, %2;"
                 :: "r"(dst), "l"(src), "r"(src_bytes));
}
#define CP_COMMIT() asm volatile("cp.async.commit_group;" ::: "memory")
#define CP_WAIT(n)  asm volatile("cp.async.wait_group %0;" :: "n"(n) : "memory")

__device__ __forceinline__ void ldsm_x4(uint32_t& r0, uint32_t& r1, uint32_t& r2,
                                        uint32_t& r3, uint32_t addr) {
    asm volatile("ldmatrix.sync.aligned.m8n8.x4.shared.b16 {%0,%1,%2,%3}, [%4];"
                 : "=r"(r0), "=r"(r1), "=r"(r2), "=r"(r3) : "r"(addr));
}
__device__ __forceinline__ void mma_fp16(float& c0, float& c1, float& c2, float& c3,
                                         uint32_t a0, uint32_t a1, uint32_t a2, uint32_t a3,
                                         uint32_t b0, uint32_t b1) {
    asm volatile(
        "mma.sync.aligned.m16n8k16.row.col.f32.f16.f16.f32 "
        "{%0,%1,%2,%3}, {%4,%5,%6,%7}, {%8,%9}, {%0,%1,%2,%3};"
        : "+f"(c0), "+f"(c1), "+f"(c2), "+f"(c3)
        : "r"(a0), "r"(a1), "r"(a2), "r"(a3), "r"(b0), "r"(b1));
}
__device__ __forceinline__ void split_store16(float v, __half* row, int j) {
    __half hi = __float2half(v);
    __half lo = __float2half(v - __half2float(hi));
    row[j] = hi;
    row[64 + j] = lo;
}

// ---------------- node MLP (x, x-split, B for step 0, agg init, BN zero) ----------------
__global__ void node_mlp(const float* __restrict__ nf, const float* __restrict__ W0,
                         const float* __restrict__ b0, const float* __restrict__ be2,
                         const float* __restrict__ conv_bias) {
    int n = blockIdx.x;
    int h = threadIdx.x;
    __shared__ float xs[DIN];
    __shared__ float vs[64];
    if (n == 0) { g_sum[h] = 0.f; g_sumsq[h] = 0.f; }
    xs[h] = nf[n * DIN + h];
    __syncthreads();
    float acc = b0[h];
#pragma unroll
    for (int i = 0; i < DIN; i++) acc += xs[i] * W0[i * H + h];
    float v = fmaxf(acc, 0.0f);
    g_x[n * H + h] = v;
    split_store16(v, g_xc + n * KC2, h);
    g_agg[n * H + h] = conv_bias[h];
    vs[h] = v;
    __syncthreads();
    float accB = 0.f;
#pragma unroll
    for (int j = 0; j < 64; j++) accB += vs[j] * be2[j * 64 + h];
    g_B[n * 64 + h] = accB;
}

// ---------------- edge hidden -> fp16 2-term split ----------------
__global__ void edge_h1(const float* __restrict__ ef, const float* __restrict__ We1,
                        const float* __restrict__ be1) {
    int gid = blockIdx.x * blockDim.x + threadIdx.x;
    int e = gid >> 7;
    int k = gid & 127;
    if (e >= N_EDGES) return;
    float acc = be1[k];
#pragma unroll
    for (int i = 0; i < EIN; i++) acc += ef[e * EIN + i] * We1[i * EH + k];
    float v = fmaxf(acc, 0.0f);
    __half hi = __float2half(v);
    __half lo = __float2half(v - __half2float(hi));
    g_h1s[(size_t)e * 256 + k] = hi;
    g_h1s[(size_t)e * 256 + 128 + k] = lo;
}

// ---------------- W' prep: col' = o*128 + k; row = [W_hi | W_hi] ----------------
__global__ void wt_prep(const float* __restrict__ We2) {
    int idx = blockIdx.x * blockDim.x + threadIdx.x;
    if (idx >= TCOLS * 64) return;
    int colp = idx >> 6;
    int j = idx & 63;
    int k = colp & 127;
    int o = colp >> 7;
    float v = We2[k * 4096 + j * 64 + o];
    __half hi = __float2half(v);
    __half* row = g_WtC + colp * KC2;
    row[j] = hi;
    row[64 + j] = hi;
}

// ---------------- edge sort by src ----------------
__global__ void zero_bins() {
    int i = blockIdx.x * blockDim.x + threadIdx.x;
    if (i < N_NODES) { g_cnt[i] = 0; g_fill[i] = 0; }
}
__global__ void hist_kernel(const int* __restrict__ src) {
    int e = blockIdx.x * blockDim.x + threadIdx.x;
    if (e < N_EDGES) atomicAdd(&g_cnt[src[e]], 1);
}
__global__ void scan_kernel() {
    __shared__ int ts[1024];
    int t = threadIdx.x;
    int base = t * 10;
    int c[10];
    int tot = 0;
#pragma unroll
    for (int i = 0; i < 10; i++) {
        int idx = base + i;
        c[i] = (idx < N_NODES) ? g_cnt[idx] : 0;
        tot += c[i];
    }
    ts[t] = tot;
    __syncthreads();
    for (int off = 1; off < 1024; off <<= 1) {
        int v = (t >= off) ? ts[t - off] : 0;
        __syncthreads();
        ts[t] += v;
        __syncthreads();
    }
    int run = ts[t] - tot;
#pragma unroll
    for (int i = 0; i < 10; i++) {
        int idx = base + i;
        if (idx < N_NODES) { g_rowptr[idx] = run; run += c[i]; }
    }
    if (t == 1023) g_rowptr[N_NODES] = N_EDGES;
}
__global__ void scatter_kernel(const int* __restrict__ src) {
    int e = blockIdx.x * blockDim.x + threadIdx.x;
    if (e >= N_EDGES) return;
    int s = src[e];
    int pos = g_rowptr[s] + atomicAdd(&g_fill[s], 1);
    g_eidx[pos] = e;
}

// ---------------- T-GEMM: 2-pass fp16, K=128 ----------------
#define BKT 64
#define STAGE_BYTES 32768
#define TG_SMEM (2 * STAGE_BYTES)
#define NKT2 2

__global__ void __launch_bounds__(128, 2) tgemm() {
    extern __shared__ char smem[];
    const uint32_t sbase = smem_u32(smem);
    const int tid = threadIdx.x;
    const int wid = tid >> 5;
    const int lane = tid & 31;
    const int block_n = blockIdx.x * 128;
    const int block_m = blockIdx.y * 128;

    const int wm = wid & 1;
    const int wn = wid >> 1;
    const int m_off = wm * 64;
    const int n_off = wn * 64;

    float acc[4][8][4];
#pragma unroll
    for (int mt = 0; mt < 4; mt++)
#pragma unroll
        for (int nt = 0; nt < 8; nt++)
#pragma unroll
            for (int q = 0; q < 4; q++) acc[mt][nt][q] = 0.0f;

    auto load_stage = [&](int stage, int kt) {
        const int k0 = kt * BKT;
        const uint32_t As = sbase + stage * STAGE_BYTES;
        const uint32_t Bs = As + 16384;
#pragma unroll
        for (int i = 0; i < 8; i++) {
            int cid = tid + i * 128;
            int r = cid >> 3;
            int c = cid & 7;
            int n = block_m + r;
            const void* gsrc = g_xc + (size_t)n * KC2 + k0 + c * 8;
            uint32_t sdst = As + r * 128 + ((c ^ (r & 7)) << 4);
            cp_async16(sdst, gsrc, (n < N_NODES) ? 16 : 0);
        }
#pragma unroll
        for (int i = 0; i < 8; i++) {
            int cid = tid + i * 128;
            int r = cid >> 3;
            int c = cid & 7;
            int col = block_n + r;
            const void* gsrc = g_WtC + (size_t)col * KC2 + k0 + c * 8;
            uint32_t sdst = Bs + r * 128 + ((c ^ (r & 7)) << 4);
            cp_async16(sdst, gsrc, 16);
        }
    };

    const int a_row_l = lane & 15;
    const int a_uoff = lane >> 4;
    const int b_row_l = ((lane >> 4) << 3) + (lane & 7);
    const int b_uoff = (lane >> 3) & 1;

    load_stage(0, 0);
    CP_COMMIT();
    load_stage(1, 1);
    CP_COMMIT();

#pragma unroll
    for (int kt = 0; kt < NKT2; kt++) {
        if (kt == NKT2 - 1) { CP_WAIT(0); } else { CP_WAIT(1); }
        __syncthreads();
        const uint32_t As = sbase + (kt & 1) * STAGE_BYTES;
        const uint32_t Bs = As + 16384;
#pragma unroll
        for (int ks = 0; ks < 4; ks++) {
            const int ub = ks * 2;
            uint32_t a[4][4];
#pragma unroll
            for (int mt = 0; mt < 4; mt++) {
                int r = m_off + mt * 16 + a_row_l;
                int u = ub + a_uoff;
                ldsm_x4(a[mt][0], a[mt][1], a[mt][2], a[mt][3],
                        As + r * 128 + ((u ^ (r & 7)) << 4));
            }
            uint32_t b[8][2];
#pragma unroll
            for (int np = 0; np < 4; np++) {
                int r = n_off + np * 16 + b_row_l;
                int u = ub + b_uoff;
                uint32_t r0, r1, r2, r3;
                ldsm_x4(r0, r1, r2, r3, Bs + r * 128 + ((u ^ (r & 7)) << 4));
                b[np * 2][0] = r0; b[np * 2][1] = r1;
                b[np * 2 + 1][0] = r2; b[np * 2 + 1][1] = r3;
            }
#pragma unroll
            for (int mt = 0; mt < 4; mt++)
#pragma unroll
                for (int nt = 0; nt < 8; nt++)
                    mma_fp16(acc[mt][nt][0], acc[mt][nt][1], acc[mt][nt][2], acc[mt][nt][3],
                             a[mt][0], a[mt][1], a[mt][2], a[mt][3],
                             b[nt][0], b[nt][1]);
        }
        __syncthreads();
    }

    const int qrow = lane >> 2;
    const int qcol = (lane & 3) * 2;
#pragma unroll
    for (int mt = 0; mt < 4; mt++) {
        int r0 = block_m + m_off + mt * 16 + qrow;
        int r1 = r0 + 8;
#pragma unroll
        for (int nt = 0; nt < 8; nt++) {
            int col = block_n + n_off + nt * 8 + qcol;
            if (r0 < N_NODES)
                *(__half2*)(g_T + (size_t)r0 * TCOLS + col) =
                    __floats2half2_rn(acc[mt][nt][0], acc[mt][nt][1]);
            if (r1 < N_NODES)
                *(__half2*)(g_T + (size_t)r1 * TCOLS + col) =
                    __floats2half2_rn(acc[mt][nt][2], acc[mt][nt][3]);
        }
    }
}

// ---------------- msg v4: grid-stride, double-buffered T prefetch ----------------
#define MT_OFF 0            // 2 x 16384
#define MH_OFF 32768        // 8192
#define MDS_OFF 40960       // 64
#define MBS_OFF 41024       // 256
#define MSG_SMEM 41280
#define MSG_GRID 740        // 148 SMs x 5 CTAs

__global__ void __launch_bounds__(128) msg_kernel4(const int* __restrict__ dst) {
    __shared__ __align__(16) char sm[MSG_SMEM];
    const uint32_t sbase = smem_u32(sm);
    int tid = threadIdx.x;
    int wn = tid >> 5;
    int lane = tid & 31;
    int* ds = (int*)(sm + MDS_OFF);
    float* Bs = (float*)(sm + MBS_OFF);

    auto prefetchT = [&](int node, int buf) {
        const char* src = (const char*)(g_T + (size_t)node * TCOLS);
        uint32_t dbase = sbase + MT_OFF + buf * 16384;
#pragma unroll
        for (int i = 0; i < 8; i++) {
            int idx = tid + i * 128;
            int r = idx >> 4;
            int u = idx & 15;
            int su = (u & 8) | ((u ^ r) & 7);
            cp_async16(dbase + r * 256 + su * 16, src + idx * 16, 16);
        }
    };

    int node = blockIdx.x;
    const int stride = gridDim.x;
    if (node >= N_NODES) return;
    prefetchT(node, 0);
    CP_COMMIT();

    const int arow = lane & 15;
    const int auoff = lane >> 4;

    int it = 0;
    for (; node < N_NODES; node += stride, it++) {
        int nxt = node + stride;
        int buf = it & 1;
        if (nxt < N_NODES) {
            prefetchT(nxt, buf ^ 1);
            CP_COMMIT();
            CP_WAIT(1);
        } else {
            CP_WAIT(0);
        }
        if (tid < 64) Bs[tid] = g_B[node * 64 + tid];
        __syncthreads();

        int beg = g_rowptr[node];
        int end = g_rowptr[node + 1];
        if (beg < end) {
            const uint32_t Tb = sbase + MT_OFF + buf * 16384;
            uint32_t bf[8][4];
            int brow = wn * 16 + ((lane >> 4) << 3) + (lane & 7);
            int uoff = (lane >> 3) & 1;
#pragma unroll
            for (int kc = 0; kc < 8; kc++) {
                int u = kc * 2 + uoff;
                int su = (u & 8) | ((u ^ brow) & 7);
                ldsm_x4(bf[kc][0], bf[kc][1], bf[kc][2], bf[kc][3],
                        Tb + brow * 256 + su * 16);
            }

            for (int base = beg; base < end; base += 16) {
                int ne = end - base;
                if (ne > 16) ne = 16;
                if (tid < 16) ds[tid] = (tid < ne) ? dst[g_eidx[base + tid]] : 0;
#pragma unroll
                for (int i = 0; i < 4; i++) {
                    int idx = tid + i * 128;
                    int r = idx >> 5;
                    int u = idx & 31;
                    uint4 v = make_uint4(0, 0, 0, 0);
                    if (r < ne) {
                        int e = g_eidx[base + r];
                        v = *(const uint4*)(g_h1s + (size_t)e * 256 + u * 8);
                    }
                    int su = (u & 24) | ((u ^ r) & 7);
                    *(uint4*)(sm + MH_OFF + r * 512 + su * 16) = v;
                }
                __syncthreads();

                float c0[4] = {0.f, 0.f, 0.f, 0.f};
                float c1[4] = {0.f, 0.f, 0.f, 0.f};
#pragma unroll
                for (int kc = 0; kc < 16; kc++) {
                    int u = kc * 2 + auoff;
                    int su = (u & 24) | ((u ^ arow) & 7);
                    uint32_t a0, a1, a2, a3;
                    ldsm_x4(a0, a1, a2, a3, sbase + MH_OFF + arow * 512 + su * 16);
                    int bk = kc & 7;
                    mma_fp16(c0[0], c0[1], c0[2], c0[3], a0, a1, a2, a3,
                             bf[bk][0], bf[bk][1]);
                    mma_fp16(c1[0], c1[1], c1[2], c1[3], a0, a1, a2, a3,
                             bf[bk][2], bf[bk][3]);
                }

                int r0 = lane >> 2;
#pragma unroll
                for (int nt = 0; nt < 2; nt++) {
                    int col = wn * 16 + nt * 8 + 2 * (lane & 3);
                    float bx = Bs[col];
                    float by = Bs[col + 1];
                    const float* cc = nt ? c1 : c0;
                    if (r0 < ne) {
                        int dd = ds[r0];
                        atomicAdd(&g_agg[dd * H + col], cc[0] + bx);
                        atomicAdd(&g_agg[dd * H + col + 1], cc[1] + by);
                    }
                    if (r0 + 8 < ne) {
                        int dd = ds[r0 + 8];
                        atomicAdd(&g_agg[dd * H + col], cc[2] + bx);
                        atomicAdd(&g_agg[dd * H + col + 1], cc[3] + by);
                    }
                }
                __syncthreads();
            }
        }
        __syncthreads();  // all warps done with buf + Bs before next iteration
    }
}

// ---------------- relu step for steps 0..STEPS-2 (4 nodes/CTA) ----------------
__global__ void __launch_bounds__(256) relu_step_b(const float* __restrict__ be2,
                                                   const float* __restrict__ conv_bias) {
    int tid = threadIdx.x;
    int sub = tid >> 6;
    int o = tid & 63;
    int n = blockIdx.x * 4 + sub;
    __shared__ float xs[4][64];
    float v = fmaxf(g_agg[n * 64 + o], 0.0f);
    g_x[n * 64 + o] = v;
    split_store16(v, g_xc + n * KC2, o);
    g_agg[n * 64 + o] = conv_bias[o];
    xs[sub][o] = v;
    __syncthreads();
    float acc = 0.f;
#pragma unroll
    for (int j = 0; j < 64; j++) acc += xs[sub][j] * be2[j * 64 + o];
    g_B[n * 64 + o] = acc;
}

// ---------------- final step: relu + BN partial sums ----------------
__global__ void __launch_bounds__(256) relu_bn() {
    int t = threadIdx.x;
    int h = t & 63;
    int rsub = t >> 6;
    float s = 0.f, q = 0.f;
    for (int r = blockIdx.x * 4 + rsub; r < N_NODES; r += gridDim.x * 4) {
        float v = fmaxf(g_agg[r * H + h], 0.0f);
        g_x[r * H + h] = v;
        s += v;
        q += v * v;
    }
    __shared__ float ss[256], sq[256];
    ss[t] = s;
    sq[t] = q;
    __syncthreads();
    if (t < 64) {
        s = ss[t] + ss[t + 64] + ss[t + 128] + ss[t + 192];
        q = sq[t] + sq[t + 64] + sq[t + 128] + sq[t + 192];
        atomicAdd(&g_sum[h], s);
        atomicAdd(&g_sumsq[h], q);
    }
}

__global__ void bn_apply(const float* __restrict__ gamma, const float* __restrict__ beta,
                         float* __restrict__ out) {
    int i = blockIdx.x * blockDim.x + threadIdx.x;
    if (i >= N_NODES * H) return;
    int h = i & 63;
    float mean = g_sum[h] / (float)N_NODES;
    float var = g_sumsq[h] / (float)N_NODES - mean * mean;
    out[i] = (g_x[i] - mean) * rsqrtf(var + 1e-5f) * gamma[h] + beta[h];
}

// ---------------- launch ----------------
extern "C" void kernel_launch(void* const* d_in, const int* in_sizes, int n_in,
                              void* d_out, int out_size) {
    const float* n_feat    = (const float*)d_in[0];
    const float* e_feat    = (const float*)d_in[1];
    const int*   src       = (const int*)d_in[2];
    const int*   dst       = (const int*)d_in[3];
    const float* W0        = (const float*)d_in[4];
    const float* b0        = (const float*)d_in[5];
    const float* We1       = (const float*)d_in[6];
    const float* be1       = (const float*)d_in[7];
    const float* We2       = (const float*)d_in[8];
    const float* be2       = (const float*)d_in[9];
    const float* conv_bias = (const float*)d_in[10];
    const float* gamma     = (const float*)d_in[11];
    const float* beta      = (const float*)d_in[12];
    float* out = (float*)d_out;

    static cudaStream_t s_aux = nullptr;
    static cudaEvent_t ev_fork = nullptr, ev_join = nullptr;
    if (!s_aux) {
        cudaStreamCreateWithFlags(&s_aux, cudaStreamNonBlocking);
        cudaEventCreateWithFlags(&ev_fork, cudaEventDisableTiming);
        cudaEventCreateWithFlags(&ev_join, cudaEventDisableTiming);
    }

    cudaFuncSetAttribute(tgemm, cudaFuncAttributeMaxDynamicSharedMemorySize, TG_SMEM);

    // fork: sort chain on aux; node/weight/edge prep on main
    cudaEventRecord(ev_fork, 0);
    cudaStreamWaitEvent(s_aux, ev_fork, 0);
    zero_bins<<<(N_NODES + 255) / 256, 256, 0, s_aux>>>();
    hist_kernel<<<(N_EDGES + 255) / 256, 256, 0, s_aux>>>(src);
    scan_kernel<<<1, 1024, 0, s_aux>>>();
    scatter_kernel<<<(N_EDGES + 255) / 256, 256, 0, s_aux>>>(src);
    cudaEventRecord(ev_join, s_aux);

    node_mlp<<<N_NODES, 64>>>(n_feat, W0, b0, be2, conv_bias);
    wt_prep<<<(TCOLS * 64) / 256, 256>>>(We2);
    edge_h1<<<(N_EDGES * EH) / 256, 256>>>(e_feat, We1, be1);
    cudaStreamWaitEvent(0, ev_join, 0);

    int nh = N_NODES * H;
    dim3 tgrid(TCOLS / 128, (N_NODES + 127) / 128);
    for (int step = 0; step < STEPS; step++) {
        tgemm<<<tgrid, 128, TG_SMEM>>>();
        msg_kernel4<<<MSG_GRID, 128>>>(dst);
        if (step < STEPS - 1) {
            relu_step_b<<<N_NODES / 4, 256>>>(be2, conv_bias);
        } else {
            relu_bn<<<100, 256>>>();
        }
    }

    bn_apply<<<(nh + 255) / 256, 256>>>(gamma, beta, out);
    (void)in_sizes; (void)n_in; (void)out_size;
}

// round 17
// speedup vs baseline: 1.2403x; 1.0574x over previous
#include <cuda_runtime.h>
#include <cuda_bf16.h>
#include <cuda_fp16.h>
#include <cstdint>

#define N_NODES 10000
#define N_EDGES 100000
#define DIN 64
#define H 64
#define EIN 16
#define EH 128
#define STEPS 3
#define KC2 128          // fp16 2-pass split K
#define TCOLS 8192

// ---------------- device scratch ----------------
__device__ float g_x[N_NODES * H];
__device__ __half g_xc[N_NODES * KC2];            // [x_hi(64) | x_lo(64)]
__device__ float g_agg[N_NODES * H];
__device__ __half g_h1s[(size_t)N_EDGES * 256];   // h1 fp16 split [hi(128)|lo(128)]
__device__ __half g_WtC[TCOLS * KC2];             // col'=o*128+k: [W_hi | W_hi]
__device__ __half g_T[(size_t)N_NODES * TCOLS];   // per node: [o][k] k-contiguous
__device__ float g_B[N_NODES * H];
__device__ int g_cnt[N_NODES];
__device__ int g_fill[N_NODES];
__device__ int g_rowptr[N_NODES + 1];
__device__ int g_eidx[N_EDGES];
__device__ float g_sum[H];
__device__ float g_sumsq[H];

// ---------------- helpers ----------------
__device__ __forceinline__ uint32_t smem_u32(const void* p) {
    uint32_t a;
    asm("{ .reg .u64 t; cvta.to.shared.u64 t, %1; cvt.u32.u64 %0, t; }" : "=r"(a) : "l"(p));
    return a;
}
__device__ __forceinline__ void cp_async16(uint32_t dst, const void* src, int src_bytes) {
    asm volatile("cp.async.cg.shared.global [%0], [%1], 16, %2;"
                 :: "r"(dst), "l"(src), "r"(src_bytes));
}
#define CP_COMMIT() asm volatile("cp.async.commit_group;" ::: "memory")
#define CP_WAIT(n)  asm volatile("cp.async.wait_group %0;" :: "n"(n) : "memory")

__device__ __forceinline__ void ldsm_x4(uint32_t& r0, uint32_t& r1, uint32_t& r2,
                                        uint32_t& r3, uint32_t addr) {
    asm volatile("ldmatrix.sync.aligned.m8n8.x4.shared.b16 {%0,%1,%2,%3}, [%4];"
                 : "=r"(r0), "=r"(r1), "=r"(r2), "=r"(r3) : "r"(addr));
}
__device__ __forceinline__ void mma_fp16(float& c0, float& c1, float& c2, float& c3,
                                         uint32_t a0, uint32_t a1, uint32_t a2, uint32_t a3,
                                         uint32_t b0, uint32_t b1) {
    asm volatile(
        "mma.sync.aligned.m16n8k16.row.col.f32.f16.f16.f32 "
        "{%0,%1,%2,%3}, {%4,%5,%6,%7}, {%8,%9}, {%0,%1,%2,%3};"
        : "+f"(c0), "+f"(c1), "+f"(c2), "+f"(c3)
        : "r"(a0), "r"(a1), "r"(a2), "r"(a3), "r"(b0), "r"(b1));
}
__device__ __forceinline__ void split_store16(float v, __half* row, int j) {
    __half hi = __float2half(v);
    __half lo = __float2half(v - __half2float(hi));
    row[j] = hi;
    row[64 + j] = lo;
}

// ---------------- node MLP (x, x-split, B for step 0, agg init, BN zero) ----------------
__global__ void node_mlp(const float* __restrict__ nf, const float* __restrict__ W0,
                         const float* __restrict__ b0, const float* __restrict__ be2,
                         const float* __restrict__ conv_bias) {
    int n = blockIdx.x;
    int h = threadIdx.x;
    __shared__ float xs[DIN];
    __shared__ float vs[64];
    if (n == 0) { g_sum[h] = 0.f; g_sumsq[h] = 0.f; }
    xs[h] = nf[n * DIN + h];
    __syncthreads();
    float acc = b0[h];
#pragma unroll
    for (int i = 0; i < DIN; i++) acc += xs[i] * W0[i * H + h];
    float v = fmaxf(acc, 0.0f);
    g_x[n * H + h] = v;
    split_store16(v, g_xc + n * KC2, h);
    g_agg[n * H + h] = conv_bias[h];
    vs[h] = v;
    __syncthreads();
    float accB = 0.f;
#pragma unroll
    for (int j = 0; j < 64; j++) accB += vs[j] * be2[j * 64 + h];
    g_B[n * 64 + h] = accB;
}

// ---------------- edge hidden -> fp16 2-term split ----------------
__global__ void edge_h1(const float* __restrict__ ef, const float* __restrict__ We1,
                        const float* __restrict__ be1) {
    int gid = blockIdx.x * blockDim.x + threadIdx.x;
    int e = gid >> 7;
    int k = gid & 127;
    if (e >= N_EDGES) return;
    float acc = be1[k];
#pragma unroll
    for (int i = 0; i < EIN; i++) acc += ef[e * EIN + i] * We1[i * EH + k];
    float v = fmaxf(acc, 0.0f);
    __half hi = __float2half(v);
    __half lo = __float2half(v - __half2float(hi));
    g_h1s[(size_t)e * 256 + k] = hi;
    g_h1s[(size_t)e * 256 + 128 + k] = lo;
}

// ---------------- W' prep: col' = o*128 + k; row = [W_hi | W_hi] ----------------
__global__ void wt_prep(const float* __restrict__ We2) {
    int idx = blockIdx.x * blockDim.x + threadIdx.x;
    if (idx >= TCOLS * 64) return;
    int colp = idx >> 6;
    int j = idx & 63;
    int k = colp & 127;
    int o = colp >> 7;
    float v = We2[k * 4096 + j * 64 + o];
    __half hi = __float2half(v);
    __half* row = g_WtC + colp * KC2;
    row[j] = hi;
    row[64 + j] = hi;
}

// ---------------- edge sort by src ----------------
__global__ void zero_bins() {
    int i = blockIdx.x * blockDim.x + threadIdx.x;
    if (i < N_NODES) { g_cnt[i] = 0; g_fill[i] = 0; }
}
__global__ void hist_kernel(const int* __restrict__ src) {
    int e = blockIdx.x * blockDim.x + threadIdx.x;
    if (e < N_EDGES) atomicAdd(&g_cnt[src[e]], 1);
}
__global__ void scan_kernel() {
    __shared__ int ts[1024];
    int t = threadIdx.x;
    int base = t * 10;
    int c[10];
    int tot = 0;
#pragma unroll
    for (int i = 0; i < 10; i++) {
        int idx = base + i;
        c[i] = (idx < N_NODES) ? g_cnt[idx] : 0;
        tot += c[i];
    }
    ts[t] = tot;
    __syncthreads();
    for (int off = 1; off < 1024; off <<= 1) {
        int v = (t >= off) ? ts[t - off] : 0;
        __syncthreads();
        ts[t] += v;
        __syncthreads();
    }
    int run = ts[t] - tot;
#pragma unroll
    for (int i = 0; i < 10; i++) {
        int idx = base + i;
        if (idx < N_NODES) { g_rowptr[idx] = run; run += c[i]; }
    }
    if (t == 1023) g_rowptr[N_NODES] = N_EDGES;
}
__global__ void scatter_kernel(const int* __restrict__ src) {
    int e = blockIdx.x * blockDim.x + threadIdx.x;
    if (e >= N_EDGES) return;
    int s = src[e];
    int pos = g_rowptr[s] + atomicAdd(&g_fill[s], 1);
    g_eidx[pos] = e;
}

// ---------------- T-GEMM: 2-pass fp16, K=128, 3 CTA/SM ----------------
#define BKT 64
#define STAGE_BYTES 32768
#define TG_SMEM (2 * STAGE_BYTES)
#define NKT2 2

__global__ void __launch_bounds__(128, 3) tgemm() {
    extern __shared__ char smem[];
    const uint32_t sbase = smem_u32(smem);
    const int tid = threadIdx.x;
    const int wid = tid >> 5;
    const int lane = tid & 31;
    const int block_n = blockIdx.x * 128;
    const int block_m = blockIdx.y * 128;

    const int wm = wid & 1;
    const int wn = wid >> 1;
    const int m_off = wm * 64;
    const int n_off = wn * 64;

    float acc[4][8][4];
#pragma unroll
    for (int mt = 0; mt < 4; mt++)
#pragma unroll
        for (int nt = 0; nt < 8; nt++)
#pragma unroll
            for (int q = 0; q < 4; q++) acc[mt][nt][q] = 0.0f;

    auto load_stage = [&](int stage, int kt) {
        const int k0 = kt * BKT;
        const uint32_t As = sbase + stage * STAGE_BYTES;
        const uint32_t Bs = As + 16384;
#pragma unroll
        for (int i = 0; i < 8; i++) {
            int cid = tid + i * 128;
            int r = cid >> 3;
            int c = cid & 7;
            int n = block_m + r;
            const void* gsrc = g_xc + (size_t)n * KC2 + k0 + c * 8;
            uint32_t sdst = As + r * 128 + ((c ^ (r & 7)) << 4);
            cp_async16(sdst, gsrc, (n < N_NODES) ? 16 : 0);
        }
#pragma unroll
        for (int i = 0; i < 8; i++) {
            int cid = tid + i * 128;
            int r = cid >> 3;
            int c = cid & 7;
            int col = block_n + r;
            const void* gsrc = g_WtC + (size_t)col * KC2 + k0 + c * 8;
            uint32_t sdst = Bs + r * 128 + ((c ^ (r & 7)) << 4);
            cp_async16(sdst, gsrc, 16);
        }
    };

    const int a_row_l = lane & 15;
    const int a_uoff = lane >> 4;
    const int b_row_l = ((lane >> 4) << 3) + (lane & 7);
    const int b_uoff = (lane >> 3) & 1;

    load_stage(0, 0);
    CP_COMMIT();
    load_stage(1, 1);
    CP_COMMIT();

#pragma unroll
    for (int kt = 0; kt < NKT2; kt++) {
        if (kt == NKT2 - 1) { CP_WAIT(0); } else { CP_WAIT(1); }
        __syncthreads();
        const uint32_t As = sbase + (kt & 1) * STAGE_BYTES;
        const uint32_t Bs = As + 16384;
#pragma unroll
        for (int ks = 0; ks < 4; ks++) {
            const int ub = ks * 2;
            uint32_t a[4][4];
#pragma unroll
            for (int mt = 0; mt < 4; mt++) {
                int r = m_off + mt * 16 + a_row_l;
                int u = ub + a_uoff;
                ldsm_x4(a[mt][0], a[mt][1], a[mt][2], a[mt][3],
                        As + r * 128 + ((u ^ (r & 7)) << 4));
            }
            uint32_t b[8][2];
#pragma unroll
            for (int np = 0; np < 4; np++) {
                int r = n_off + np * 16 + b_row_l;
                int u = ub + b_uoff;
                uint32_t r0, r1, r2, r3;
                ldsm_x4(r0, r1, r2, r3, Bs + r * 128 + ((u ^ (r & 7)) << 4));
                b[np * 2][0] = r0; b[np * 2][1] = r1;
                b[np * 2 + 1][0] = r2; b[np * 2 + 1][1] = r3;
            }
#pragma unroll
            for (int mt = 0; mt < 4; mt++)
#pragma unroll
                for (int nt = 0; nt < 8; nt++)
                    mma_fp16(acc[mt][nt][0], acc[mt][nt][1], acc[mt][nt][2], acc[mt][nt][3],
                             a[mt][0], a[mt][1], a[mt][2], a[mt][3],
                             b[nt][0], b[nt][1]);
        }
        __syncthreads();
    }

    const int qrow = lane >> 2;
    const int qcol = (lane & 3) * 2;
#pragma unroll
    for (int mt = 0; mt < 4; mt++) {
        int r0 = block_m + m_off + mt * 16 + qrow;
        int r1 = r0 + 8;
#pragma unroll
        for (int nt = 0; nt < 8; nt++) {
            int col = block_n + n_off + nt * 8 + qcol;
            if (r0 < N_NODES)
                *(__half2*)(g_T + (size_t)r0 * TCOLS + col) =
                    __floats2half2_rn(acc[mt][nt][0], acc[mt][nt][1]);
            if (r1 < N_NODES)
                *(__half2*)(g_T + (size_t)r1 * TCOLS + col) =
                    __floats2half2_rn(acc[mt][nt][2], acc[mt][nt][3]);
        }
    }
}

// ---------------- msg v3: tensor-core per-node GEMM, 16-edge chunks ----------------
#define MSG_T_OFF 0
#define MSG_H_OFF 16384
#define MSG_DS_OFF 24576
#define MSG_BS_OFF 24640
#define MSG_SMEM 24896

__global__ void __launch_bounds__(128) msg_kernel3(const int* __restrict__ dst) {
    __shared__ __align__(16) char sm[MSG_SMEM];
    int s = blockIdx.x;
    int beg = g_rowptr[s];
    int end = g_rowptr[s + 1];
    if (beg == end) return;
    const uint32_t sbase = smem_u32(sm);
    int tid = threadIdx.x;
    int wn = tid >> 5;
    int lane = tid & 31;
    int* ds = (int*)(sm + MSG_DS_OFF);
    float* Bs = (float*)(sm + MSG_BS_OFF);

    const uint4* Tg = (const uint4*)(g_T + (size_t)s * TCOLS);
#pragma unroll
    for (int i = 0; i < 8; i++) {
        int idx = tid + i * 128;
        int r = idx >> 4;
        int u = idx & 15;
        int su = (u & 8) | ((u ^ r) & 7);
        *(uint4*)(sm + MSG_T_OFF + r * 256 + su * 16) = Tg[idx];
    }
    if (tid < 64) Bs[tid] = g_B[s * 64 + tid];
    __syncthreads();

    uint32_t bf[8][4];
    {
        int brow = wn * 16 + ((lane >> 4) << 3) + (lane & 7);
        int uoff = (lane >> 3) & 1;
#pragma unroll
        for (int kc = 0; kc < 8; kc++) {
            int u = kc * 2 + uoff;
            int su = (u & 8) | ((u ^ brow) & 7);
            ldsm_x4(bf[kc][0], bf[kc][1], bf[kc][2], bf[kc][3],
                    sbase + MSG_T_OFF + brow * 256 + su * 16);
        }
    }

    const int arow = lane & 15;
    const int auoff = lane >> 4;

    for (int base = beg; base < end; base += 16) {
        int ne = end - base;
        if (ne > 16) ne = 16;
        if (tid < 16) ds[tid] = (tid < ne) ? dst[g_eidx[base + tid]] : 0;
#pragma unroll
        for (int i = 0; i < 4; i++) {
            int idx = tid + i * 128;
            int r = idx >> 5;
            int u = idx & 31;
            uint4 v = make_uint4(0, 0, 0, 0);
            if (r < ne) {
                int e = g_eidx[base + r];
                v = *(const uint4*)(g_h1s + (size_t)e * 256 + u * 8);
            }
            int su = (u & 24) | ((u ^ r) & 7);
            *(uint4*)(sm + MSG_H_OFF + r * 512 + su * 16) = v;
        }
        __syncthreads();

        float c0[4] = {0.f, 0.f, 0.f, 0.f};
        float c1[4] = {0.f, 0.f, 0.f, 0.f};
#pragma unroll
        for (int kc = 0; kc < 16; kc++) {
            int u = kc * 2 + auoff;
            int su = (u & 24) | ((u ^ arow) & 7);
            uint32_t a0, a1, a2, a3;
            ldsm_x4(a0, a1, a2, a3, sbase + MSG_H_OFF + arow * 512 + su * 16);
            int bk = kc & 7;
            mma_fp16(c0[0], c0[1], c0[2], c0[3], a0, a1, a2, a3, bf[bk][0], bf[bk][1]);
            mma_fp16(c1[0], c1[1], c1[2], c1[3], a0, a1, a2, a3, bf[bk][2], bf[bk][3]);
        }

        int r0 = lane >> 2;
#pragma unroll
        for (int nt = 0; nt < 2; nt++) {
            int col = wn * 16 + nt * 8 + 2 * (lane & 3);
            float bx = Bs[col];
            float by = Bs[col + 1];
            const float* cc = nt ? c1 : c0;
            if (r0 < ne) {
                int dd = ds[r0];
                atomicAdd(&g_agg[dd * H + col], cc[0] + bx);
                atomicAdd(&g_agg[dd * H + col + 1], cc[1] + by);
            }
            if (r0 + 8 < ne) {
                int dd = ds[r0 + 8];
                atomicAdd(&g_agg[dd * H + col], cc[2] + bx);
                atomicAdd(&g_agg[dd * H + col + 1], cc[3] + by);
            }
        }
        __syncthreads();
    }
}

// ---------------- relu step for steps 0..STEPS-2 (4 nodes/CTA) ----------------
__global__ void __launch_bounds__(256) relu_step_b(const float* __restrict__ be2,
                                                   const float* __restrict__ conv_bias) {
    int tid = threadIdx.x;
    int sub = tid >> 6;
    int o = tid & 63;
    int n = blockIdx.x * 4 + sub;
    __shared__ float xs[4][64];
    float v = fmaxf(g_agg[n * 64 + o], 0.0f);
    g_x[n * 64 + o] = v;
    split_store16(v, g_xc + n * KC2, o);
    g_agg[n * 64 + o] = conv_bias[o];
    xs[sub][o] = v;
    __syncthreads();
    float acc = 0.f;
#pragma unroll
    for (int j = 0; j < 64; j++) acc += xs[sub][j] * be2[j * 64 + o];
    g_B[n * 64 + o] = acc;
}

// ---------------- final step: relu + BN partial sums ----------------
__global__ void __launch_bounds__(256) relu_bn() {
    int t = threadIdx.x;
    int h = t & 63;
    int rsub = t >> 6;
    float s = 0.f, q = 0.f;
    for (int r = blockIdx.x * 4 + rsub; r < N_NODES; r += gridDim.x * 4) {
        float v = fmaxf(g_agg[r * H + h], 0.0f);
        g_x[r * H + h] = v;
        s += v;
        q += v * v;
    }
    __shared__ float ss[256], sq[256];
    ss[t] = s;
    sq[t] = q;
    __syncthreads();
    if (t < 64) {
        s = ss[t] + ss[t + 64] + ss[t + 128] + ss[t + 192];
        q = sq[t] + sq[t + 64] + sq[t + 128] + sq[t + 192];
        atomicAdd(&g_sum[h], s);
        atomicAdd(&g_sumsq[h], q);
    }
}

__global__ void bn_apply(const float* __restrict__ gamma, const float* __restrict__ beta,
                         float* __restrict__ out) {
    int i = blockIdx.x * blockDim.x + threadIdx.x;
    if (i >= N_NODES * H) return;
    int h = i & 63;
    float mean = g_sum[h] / (float)N_NODES;
    float var = g_sumsq[h] / (float)N_NODES - mean * mean;
    out[i] = (g_x[i] - mean) * rsqrtf(var + 1e-5f) * gamma[h] + beta[h];
}

// ---------------- launch ----------------
extern "C" void kernel_launch(void* const* d_in, const int* in_sizes, int n_in,
                              void* d_out, int out_size) {
    const float* n_feat    = (const float*)d_in[0];
    const float* e_feat    = (const float*)d_in[1];
    const int*   src       = (const int*)d_in[2];
    const int*   dst       = (const int*)d_in[3];
    const float* W0        = (const float*)d_in[4];
    const float* b0        = (const float*)d_in[5];
    const float* We1       = (const float*)d_in[6];
    const float* be1       = (const float*)d_in[7];
    const float* We2       = (const float*)d_in[8];
    const float* be2       = (const float*)d_in[9];
    const float* conv_bias = (const float*)d_in[10];
    const float* gamma     = (const float*)d_in[11];
    const float* beta      = (const float*)d_in[12];
    float* out = (float*)d_out;

    static cudaStream_t s_aux = nullptr;
    static cudaEvent_t ev_fork = nullptr, ev_join = nullptr;
    if (!s_aux) {
        cudaStreamCreateWithFlags(&s_aux, cudaStreamNonBlocking);
        cudaEventCreateWithFlags(&ev_fork, cudaEventDisableTiming);
        cudaEventCreateWithFlags(&ev_join, cudaEventDisableTiming);
    }

    cudaFuncSetAttribute(tgemm, cudaFuncAttributeMaxDynamicSharedMemorySize, TG_SMEM);

    // fork: sort chain + edge_h1 on aux; node/weight prep + tgemm0 on main
    cudaEventRecord(ev_fork, 0);
    cudaStreamWaitEvent(s_aux, ev_fork, 0);
    zero_bins<<<(N_NODES + 255) / 256, 256, 0, s_aux>>>();
    hist_kernel<<<(N_EDGES + 255) / 256, 256, 0, s_aux>>>(src);
    scan_kernel<<<1, 1024, 0, s_aux>>>();
    scatter_kernel<<<(N_EDGES + 255) / 256, 256, 0, s_aux>>>(src);
    edge_h1<<<(N_EDGES * EH) / 256, 256, 0, s_aux>>>(e_feat, We1, be1);
    cudaEventRecord(ev_join, s_aux);

    node_mlp<<<N_NODES, 64>>>(n_feat, W0, b0, be2, conv_bias);
    wt_prep<<<(TCOLS * 64) / 256, 256>>>(We2);

    int nh = N_NODES * H;
    dim3 tgrid(TCOLS / 128, (N_NODES + 127) / 128);
    for (int step = 0; step < STEPS; step++) {
        tgemm<<<tgrid, 128, TG_SMEM>>>();
        if (step == 0) cudaStreamWaitEvent(0, ev_join, 0);  // msg needs sort + h1
        msg_kernel3<<<N_NODES, 128>>>(dst);
        if (step < STEPS - 1) {
            relu_step_b<<<N_NODES / 4, 256>>>(be2, conv_bias);
        } else {
            relu_bn<<<100, 256>>>();
        }
    }

    bn_apply<<<(nh + 255) / 256, 256>>>(gamma, beta, out);
    (void)in_sizes; (void)n_in; (void)out_size;
}